// round 9
// baseline (speedup 1.0000x reference)
#include <cuda_runtime.h>
#include <cstdint>

// input_ids : [131072] int32    item_codes: [1000000, 8] int32
// centroids : [8, 256, 64] f32  out: [131072, 512] f32
// out[t, m*64:(m+1)*64] = centroids[m, min(codes[ids[t],m],255)]; ids[t]==0 -> 0.
// setup guarantees centroids[:,0,:]==0 -> pad token maps to code 0, branch-free.
//
// Block-internal m-phases: stage 64 tokens' codes in smem, then each warp
// sweeps g=0..3 over its own 8 tokens. Per-phase read working set = 2 tables
// = 128KB -> L1-resident (warps phase-align naturally). Default-cache stores:
// each 2KB token row completes in L2 within ~us -> dense DRAM evictions.

static constexpr int THREADS       = 256;
static constexpr int TOK_PER_BLOCK = 64;
static constexpr int TOK_PER_WARP  = 8;

__global__ void __launch_bounds__(THREADS)
pq_blockphase_kernel(const int* __restrict__ input_ids,
                     const int* __restrict__ item_codes,
                     const float4* __restrict__ centroids4, // [8][256][16] f4
                     float4* __restrict__ out4,             // [tokens][128] f4
                     int n_tokens)
{
    __shared__ int code_sm[TOK_PER_BLOCK * 8];              // 2 KB

    const int tid  = threadIdx.x;
    const int base = blockIdx.x * TOK_PER_BLOCK;

    // ---- stage codes: threads 0..127, one int4 half-row each ----
    if (tid < 2 * TOK_PER_BLOCK) {
        const int lt   = tid >> 1;                          // 0..63
        const int half = tid & 1;
        const int t    = base + lt;
        int4 c4 = make_int4(0, 0, 0, 0);
        if (t < n_tokens) {
            const int id = __ldg(input_ids + t);
            if (id != 0) {                                  // pad -> code 0 (zero row)
                c4 = __ldg((const int4*)(item_codes + (size_t)id * 8) + half);
                c4.x = min(c4.x, 255); c4.y = min(c4.y, 255);
                c4.z = min(c4.z, 255); c4.w = min(c4.w, 255);
            }
        }
        ((int4*)code_sm)[tid] = c4;
    }
    __syncthreads();

    const int lane  = tid & 31;
    const int w     = tid >> 5;
    const int half  = lane >> 4;              // m = 2g + half
    const int e     = lane & 15;              // float4 slot within 256B row
    const int wbase = base + w * TOK_PER_WARP;

    const bool full = (wbase + TOK_PER_WARP <= n_tokens);

    // ---- 4 phases x 8 independent token slices; reads L1-hot per phase ----
    #pragma unroll
    for (int g = 0; g < 4; g++) {
        const float4* __restrict__ tab =
            centroids4 + (size_t)(2 * g + half) * 256 * 16;

        if (full) {
            #pragma unroll
            for (int i = 0; i < TOK_PER_WARP; i++) {
                const int lt = w * TOK_PER_WARP + i;
                const int c  = code_sm[lt * 8 + 2 * g + half];   // LDS broadcast
                const float4 v = __ldg(tab + c * 16 + e);        // L1-resident
                out4[(size_t)(wbase + i) * 128 + g * 32 + lane] = v; // default cache
            }
        } else {
            for (int i = 0; i < TOK_PER_WARP; i++) {
                const int t = wbase + i;
                if (t >= n_tokens) break;
                const int lt = w * TOK_PER_WARP + i;
                const int c  = code_sm[lt * 8 + 2 * g + half];
                const float4 v = __ldg(tab + c * 16 + e);
                out4[(size_t)t * 128 + g * 32 + lane] = v;
            }
        }
    }
}

extern "C" void kernel_launch(void* const* d_in, const int* in_sizes, int n_in,
                              void* d_out, int out_size)
{
    const int*    input_ids  = (const int*)d_in[0];
    const int*    item_codes = (const int*)d_in[1];
    const float4* centroids4 = (const float4*)d_in[2];
    float4*       out4       = (float4*)d_out;

    const int n_tokens = in_sizes[0];                        // 131072
    const int blocks = (n_tokens + TOK_PER_BLOCK - 1) / TOK_PER_BLOCK; // 2048

    // Maximize L1 carveout (smem use is 2KB) so two 64KB tables stay resident.
    static bool once = [] {
        cudaFuncSetAttribute(pq_blockphase_kernel,
                             cudaFuncAttributePreferredSharedMemoryCarveout,
                             cudaSharedmemCarveoutMaxL1);
        return true;
    }();
    (void)once;

    pq_blockphase_kernel<<<blocks, THREADS>>>(input_ids, item_codes,
                                              centroids4, out4, n_tokens);
}

// round 10
// speedup vs baseline: 1.1572x; 1.1572x over previous
#include <cuda_runtime.h>
#include <cstdint>

// input_ids : [256,512] int32   item_codes: [1000000,8] int32
// centroids : [8,256,64] f32    out: [131072, 512] f32
// out[t] = concat_m centroids[m, min(codes[ids[t],m],255)]; ids[t]==0 -> 0.
//
// R2 skeleton (best: 43.0us), single change: default-policy output stores
// instead of __stcs. Theory: evict-first stores fragment the 2KB row
// writebacks -> DRAM ACT amplification in the warm (graph-replay) regime;
// default policy lets L2 aggregate dense full-row writebacks.

static constexpr int PQ_M = 8;
static constexpr int F4_PER_TOKEN = 128;   // 512 floats
static constexpr int F4_PER_SUB = 16;      // 64 floats per subvector

__global__ void __launch_bounds__(256)
pq_gather_kernel(const int* __restrict__ input_ids,
                 const int* __restrict__ item_codes,
                 const float4* __restrict__ centroids4,   // [8][256][16] float4
                 float4* __restrict__ out4,               // [tokens][128] float4
                 int n_tokens)
{
    const int warp = (blockIdx.x * blockDim.x + threadIdx.x) >> 5;
    const int lane = threadIdx.x & 31;
    if (warp >= n_tokens) return;

    const int id = input_ids[warp];                 // uniform per warp (broadcast)
    float4* __restrict__ o = out4 + (size_t)warp * F4_PER_TOKEN;

    if (id == 0) {
        const float4 z = make_float4(0.f, 0.f, 0.f, 0.f);
        #pragma unroll
        for (int j = 0; j < 4; j++)
            o[lane + 32 * j] = z;
        return;
    }

    // Lanes 0..7 fetch the 8 PQ codes in one coalesced 32B sector.
    int mycode = 0;
    if (lane < PQ_M) {
        mycode = __ldg(item_codes + (size_t)id * PQ_M + lane);
        mycode = min(mycode, 255);
    }

    // Lane writes float4 slots {lane, lane+32, lane+64, lane+96}:
    // slot f -> sub-dim m = f>>4, element f&15. 2KB contiguous per warp.
    #pragma unroll
    for (int j = 0; j < 4; j++) {
        const int f = lane + 32 * j;
        const int m = f >> 4;
        const int c = __shfl_sync(0xffffffffu, mycode, m);
        const float4 v = __ldg(centroids4 + ((size_t)(m * 256 + c) * F4_PER_SUB) + (f & 15));
        o[f] = v;                                   // default cache policy
    }
}

extern "C" void kernel_launch(void* const* d_in, const int* in_sizes, int n_in,
                              void* d_out, int out_size)
{
    const int*    input_ids  = (const int*)d_in[0];
    const int*    item_codes = (const int*)d_in[1];
    const float4* centroids4 = (const float4*)d_in[2];
    float4*       out4       = (float4*)d_out;

    const int n_tokens = in_sizes[0];               // 131072
    const int warps_per_block = 256 / 32;
    const int blocks = (n_tokens + warps_per_block - 1) / warps_per_block;

    pq_gather_kernel<<<blocks, 256>>>(input_ids, item_codes, centroids4, out4,
                                      n_tokens);
}